// round 9
// baseline (speedup 1.0000x reference)
#include <cuda_runtime.h>
#include <cuda_bf16.h>
#include <cstdint>

// ---------------------------------------------------------------------------
// centercompute: per-class mean of [N, 256] f32 features (4 classes), then
// L2-normalize each class center. Output: fea_center [4,256] f32 (+ target
// arange(4) if out_size allows). Labels are int32 on device.
//
// Stage 1 (seg_sum, fused count): grid-stride over rows, 256 thr/block;
//   thread t owns float4 column (t & 63); its 4 unrolled rows are CONTIGUOUS
//   (base + (t>>6)*4 + u) so the 4 labels load as one aligned int4 (1 LDG.128
//   instead of 4 LDG.32 -> 5 LDG issues/thread/iter instead of 8).
//   64 thr/row -> warp-uniform label branch. Packed add.rn.f32x2 accumulate.
//   col==0 threads count labels (integer). Block reduce -> per-block partials.
// Stage 2 (reduce_finalize): 32 blocks x 1024 thr each sum 19 stage-1 partial
//   vectors coalesced (608 = 32*19); last block to arrive (int-atomic ticket,
//   reset each call for graph-replay determinism) sums the 32 second-level
//   partials + 608 int counts in fixed order, normalizes, writes out.
// ---------------------------------------------------------------------------

#define NB   608        // stage-1 grid (152 SMs * 4)
#define NB2  32         // reduce grid; NB = NB2 * 19
#define REDW 19
#define NCLS 4

__device__ ulonglong2 g_partials [NB  * NCLS * 64]; // [block][class][64 x float4]
__device__ float      g_partials2[NB2 * 1024];      // [block2][class*256+col]
__device__ int        g_cnt[NB * NCLS];
__device__ int        g_sem = 0;                    // last-block ticket

static __device__ __forceinline__ unsigned long long f32x2_add(
    unsigned long long a, unsigned long long b) {
    unsigned long long r;
    asm("add.rn.f32x2 %0, %1, %2;" : "=l"(r) : "l"(a), "l"(b));
    return r;
}

static __device__ __forceinline__ void vadd(ulonglong2& a, const ulonglong2& v) {
    a.x = f32x2_add(a.x, v.x);
    a.y = f32x2_add(a.y, v.y);
}

__global__ __launch_bounds__(256) void seg_sum_kernel(
    const ulonglong2* __restrict__ feat,   // [N, 64] 16B packs (256 f32/row)
    const int*        __restrict__ labels, // [N] int32
    int n)
{
    const int tid  = threadIdx.x;
    const int col  = tid & 63;   // float4 column 0..63
    const int rsub = tid >> 6;   // row-quad slot 0..3 (rows rsub*4 .. rsub*4+3)

    ulonglong2 acc[NCLS];
#pragma unroll
    for (int c = 0; c < NCLS; c++) { acc[c].x = 0ull; acc[c].y = 0ull; }
    int cnt0 = 0, cnt1 = 0, cnt2 = 0, cnt3 = 0;   // used only when col==0

    const int stride = gridDim.x * 16;
    int base = blockIdx.x * 16;

    // ---- full-tile fast path: labels as one aligned int4 per thread ----
    for (; base + 16 <= n; base += stride) {
        const int r0 = base + rsub * 4;
        const int4 lab = *reinterpret_cast<const int4*>(labels + r0); // LDG.128, warp-bcast
        ulonglong2 v[4];
#pragma unroll
        for (int u = 0; u < 4; u++)                 // 4 independent LDG.128
            v[u] = feat[(size_t)(r0 + u) * 64 + col];

        int lv[4] = {lab.x, lab.y, lab.z, lab.w};
        // ---- warp-uniform class branch: adds for ONE class per row ----
#pragma unroll
        for (int u = 0; u < 4; u++) {
            int cl = lv[u];
            if      (cl == 0) vadd(acc[0], v[u]);
            else if (cl == 1) vadd(acc[1], v[u]);
            else if (cl == 2) vadd(acc[2], v[u]);
            else if (cl == 3) vadd(acc[3], v[u]);
        }
        if (col == 0) {
#pragma unroll
            for (int u = 0; u < 4; u++) {
                cnt0 += (lv[u] == 0); cnt1 += (lv[u] == 1);
                cnt2 += (lv[u] == 2); cnt3 += (lv[u] == 3);
            }
        }
    }

    // ---- tail: guarded scalar path ----
    if (base < n) {
        const int r0 = base + rsub * 4;
#pragma unroll
        for (int u = 0; u < 4; u++) {
            int r = r0 + u;
            if (r < n) {
                int cl = labels[r];
                ulonglong2 v = feat[(size_t)r * 64 + col];
                if      (cl == 0) vadd(acc[0], v);
                else if (cl == 1) vadd(acc[1], v);
                else if (cl == 2) vadd(acc[2], v);
                else if (cl == 3) vadd(acc[3], v);
                if (col == 0) {
                    cnt0 += (cl == 0); cnt1 += (cl == 1);
                    cnt2 += (cl == 2); cnt3 += (cl == 3);
                }
            }
        }
    }

    // ---- block reduction across the 4 row slots, write partials ----
    __shared__ ulonglong2 sh[256];
#pragma unroll
    for (int c = 0; c < NCLS; c++) {
        sh[tid] = acc[c];
        __syncthreads();
        if (tid < 64) {
            ulonglong2 s = sh[tid];
            vadd(s, sh[tid + 64]);
            vadd(s, sh[tid + 128]);
            vadd(s, sh[tid + 192]);
            g_partials[((size_t)blockIdx.x * NCLS + c) * 64 + tid] = s;
        }
        __syncthreads();
    }

    // ---- integer count reduction (4 contributing threads: tid 0,64,128,192)
    __shared__ int scnt[4 * NCLS];
    if (col == 0) {
        scnt[rsub * NCLS + 0] = cnt0;
        scnt[rsub * NCLS + 1] = cnt1;
        scnt[rsub * NCLS + 2] = cnt2;
        scnt[rsub * NCLS + 3] = cnt3;
    }
    __syncthreads();
    if (tid < NCLS)
        g_cnt[blockIdx.x * NCLS + tid] =
            scnt[tid] + scnt[NCLS + tid] + scnt[2 * NCLS + tid] + scnt[3 * NCLS + tid];
}

__global__ __launch_bounds__(1024) void reduce_finalize_kernel(
    float* __restrict__ out, int out_size)
{
    const int j = threadIdx.x;           // 0..1023 (class*256 + col)
    const int c = j >> 8;                // class 0..3

    // ---- level-2 tree reduction: this block's 19 stage-1 partials ----
    {
        const int b0 = blockIdx.x * REDW;
        const float* p = reinterpret_cast<const float*>(g_partials);
        float s = 0.0f;
#pragma unroll 4
        for (int k = 0; k < REDW; k++)   // coalesced
            s += p[(size_t)(b0 + k) * 1024 + j];
        g_partials2[blockIdx.x * 1024 + j] = s;
    }
    __threadfence();

    // ---- last-block-arrives ticket (deterministic output: values are
    //      reduced in fixed order; only WHICH block finalizes varies) ----
    __shared__ int is_last;
    if (j == 0) {
        int t = atomicAdd(&g_sem, 1);
        is_last = (t == NB2 - 1);
        if (t == NB2 - 1) g_sem = 0;     // reset for next graph replay
    }
    __syncthreads();
    if (!is_last) return;
    __threadfence();                     // acquire: see all blocks' partials2

    __shared__ float scount[NCLS];
    __shared__ float wsum[32];
    __shared__ float sinv[NCLS];

    if (j < NCLS) {
        int s = 0;
        for (int b = 0; b < NB; b++) s += g_cnt[b * NCLS + j];
        scount[j] = (float)s;
    }
    __syncthreads();

    // deterministic fixed-order reduction over second-level partials
    float sum = 0.0f;
#pragma unroll 8
    for (int b = 0; b < NB2; b++)
        sum += g_partials2[b * 1024 + j];

    const float mean = sum / scount[c];

    // per-class L2 norm: 256 threads/class = 8 warps/class
    float m2 = mean * mean;
#pragma unroll
    for (int o = 16; o > 0; o >>= 1)
        m2 += __shfl_down_sync(0xFFFFFFFFu, m2, o);
    if ((j & 31) == 0) wsum[j >> 5] = m2;
    __syncthreads();
    if (j < NCLS) {
        float t = 0.0f;
#pragma unroll
        for (int w = 0; w < 8; w++) t += wsum[j * 8 + w];
        float nrm = sqrtf(t);
        sinv[j] = 1.0f / fmaxf(nrm, 1e-12f);
    }
    __syncthreads();

    if (j < out_size) out[j] = mean * sinv[c];

    // target = arange(4), appended after the 1024 center floats if present
    int k = 1024 + j;
    if (j < NCLS && k < out_size) out[k] = (float)j;
}

extern "C" void kernel_launch(void* const* d_in, const int* in_sizes, int n_in,
                              void* d_out, int out_size)
{
    const ulonglong2* feat   = (const ulonglong2*)d_in[0];  // [N,256] f32
    const int*        labels = (const int*)d_in[1];         // [N] int32
    const int n = in_sizes[1];                              // rows

    seg_sum_kernel<<<NB, 256>>>(feat, labels, n);
    reduce_finalize_kernel<<<NB2, 1024>>>((float*)d_out, out_size);
}

// round 14
// speedup vs baseline: 1.0619x; 1.0619x over previous
#include <cuda_runtime.h>
#include <cuda_bf16.h>
#include <cstdint>

// ---------------------------------------------------------------------------
// centercompute: per-class mean of [N, 256] f32 features (4 classes), then
// L2-normalize each class center. Output: fea_center [4,256] f32 (+ target
// arange(4) if out_size allows). Labels are int32 on device.
//
// Stage 1 (seg_sum, fused count): grid-stride over rows, 256 thr/block;
//   thread t owns float4 column (t & 63); its 4 unrolled rows are CONTIGUOUS
//   (base + (t>>6)*4 + u) so the 4 labels load as one aligned int4 (1 LDG.128
//   instead of 4 LDG.32). 64 thr/row -> warp-uniform label branch. Packed
//   add.rn.f32x2 accumulate. col==0 threads count labels (integer).
//   Block reduce -> per-block partials (deterministic, no float atomics).
// Stage 2 (reduce): 32 blocks x 1024 thr each sum 19 stage-1 partial vectors
//   coalesced (608 = 32*19) -> 32 x 1024 floats; threads j<4 also fold 19
//   count-vectors -> 32 x 4 ints.
// Stage 3 (finalize): 1 block x 1024 thr sums 32 second-level partials +
//   32 counts in fixed order, normalizes, writes out.
// ---------------------------------------------------------------------------

#define NB   608        // stage-1 grid (152 SMs * 4)
#define NB2  32         // reduce grid; NB = NB2 * 19
#define REDW 19
#define NCLS 4

__device__ ulonglong2 g_partials [NB  * NCLS * 64]; // [block][class][64 x float4]
__device__ float      g_partials2[NB2 * 1024];      // [block2][class*256+col]
__device__ int        g_cnt [NB  * NCLS];
__device__ int        g_cnt2[NB2 * NCLS];

static __device__ __forceinline__ unsigned long long f32x2_add(
    unsigned long long a, unsigned long long b) {
    unsigned long long r;
    asm("add.rn.f32x2 %0, %1, %2;" : "=l"(r) : "l"(a), "l"(b));
    return r;
}

static __device__ __forceinline__ void vadd(ulonglong2& a, const ulonglong2& v) {
    a.x = f32x2_add(a.x, v.x);
    a.y = f32x2_add(a.y, v.y);
}

__global__ __launch_bounds__(256) void seg_sum_kernel(
    const ulonglong2* __restrict__ feat,   // [N, 64] 16B packs (256 f32/row)
    const int*        __restrict__ labels, // [N] int32
    int n)
{
    const int tid  = threadIdx.x;
    const int col  = tid & 63;   // float4 column 0..63
    const int rsub = tid >> 6;   // row-quad slot 0..3 (rows rsub*4 .. rsub*4+3)

    ulonglong2 acc[NCLS];
#pragma unroll
    for (int c = 0; c < NCLS; c++) { acc[c].x = 0ull; acc[c].y = 0ull; }
    int cnt0 = 0, cnt1 = 0, cnt2 = 0, cnt3 = 0;   // used only when col==0

    const int stride = gridDim.x * 16;
    int base = blockIdx.x * 16;

    // ---- full-tile fast path: labels as one aligned int4 per thread ----
    for (; base + 16 <= n; base += stride) {
        const int r0 = base + rsub * 4;
        const int4 lab = *reinterpret_cast<const int4*>(labels + r0); // LDG.128, warp-bcast
        ulonglong2 v[4];
#pragma unroll
        for (int u = 0; u < 4; u++)                 // 4 independent LDG.128
            v[u] = feat[(size_t)(r0 + u) * 64 + col];

        int lv[4] = {lab.x, lab.y, lab.z, lab.w};
        // ---- warp-uniform class branch: adds for ONE class per row ----
#pragma unroll
        for (int u = 0; u < 4; u++) {
            int cl = lv[u];
            if      (cl == 0) vadd(acc[0], v[u]);
            else if (cl == 1) vadd(acc[1], v[u]);
            else if (cl == 2) vadd(acc[2], v[u]);
            else if (cl == 3) vadd(acc[3], v[u]);
        }
        if (col == 0) {
#pragma unroll
            for (int u = 0; u < 4; u++) {
                cnt0 += (lv[u] == 0); cnt1 += (lv[u] == 1);
                cnt2 += (lv[u] == 2); cnt3 += (lv[u] == 3);
            }
        }
    }

    // ---- tail: guarded scalar path ----
    if (base < n) {
        const int r0 = base + rsub * 4;
#pragma unroll
        for (int u = 0; u < 4; u++) {
            int r = r0 + u;
            if (r < n) {
                int cl = labels[r];
                ulonglong2 v = feat[(size_t)r * 64 + col];
                if      (cl == 0) vadd(acc[0], v);
                else if (cl == 1) vadd(acc[1], v);
                else if (cl == 2) vadd(acc[2], v);
                else if (cl == 3) vadd(acc[3], v);
                if (col == 0) {
                    cnt0 += (cl == 0); cnt1 += (cl == 1);
                    cnt2 += (cl == 2); cnt3 += (cl == 3);
                }
            }
        }
    }

    // ---- block reduction across the 4 row slots, write partials ----
    __shared__ ulonglong2 sh[256];
#pragma unroll
    for (int c = 0; c < NCLS; c++) {
        sh[tid] = acc[c];
        __syncthreads();
        if (tid < 64) {
            ulonglong2 s = sh[tid];
            vadd(s, sh[tid + 64]);
            vadd(s, sh[tid + 128]);
            vadd(s, sh[tid + 192]);
            g_partials[((size_t)blockIdx.x * NCLS + c) * 64 + tid] = s;
        }
        __syncthreads();
    }

    // ---- integer count reduction (4 contributing threads: tid 0,64,128,192)
    __shared__ int scnt[4 * NCLS];
    if (col == 0) {
        scnt[rsub * NCLS + 0] = cnt0;
        scnt[rsub * NCLS + 1] = cnt1;
        scnt[rsub * NCLS + 2] = cnt2;
        scnt[rsub * NCLS + 3] = cnt3;
    }
    __syncthreads();
    if (tid < NCLS)
        g_cnt[blockIdx.x * NCLS + tid] =
            scnt[tid] + scnt[NCLS + tid] + scnt[2 * NCLS + tid] + scnt[3 * NCLS + tid];
}

__global__ __launch_bounds__(1024) void reduce_kernel()
{
    const int j  = threadIdx.x;          // 0..1023 (class*256 + col)
    const int b0 = blockIdx.x * REDW;    // first stage-1 block of this slice
    const float* p = reinterpret_cast<const float*>(g_partials);

    float s = 0.0f;
#pragma unroll 4
    for (int k = 0; k < REDW; k++)       // coalesced: consecutive j -> consecutive floats
        s += p[(size_t)(b0 + k) * 1024 + j];
    g_partials2[blockIdx.x * 1024 + j] = s;

    // fold 19 count-vectors -> 1 (threads 0..3)
    if (j < NCLS) {
        int cs = 0;
#pragma unroll 4
        for (int k = 0; k < REDW; k++)
            cs += g_cnt[(b0 + k) * NCLS + j];
        g_cnt2[blockIdx.x * NCLS + j] = cs;
    }
}

__global__ __launch_bounds__(1024) void finalize_kernel(
    float* __restrict__ out, int out_size)
{
    __shared__ float scount[NCLS];
    __shared__ float wsum[32];
    __shared__ float sinv[NCLS];

    const int j = threadIdx.x;           // 0..1023
    const int c = j >> 8;                // class 0..3

    if (j < NCLS) {
        int s = 0;
#pragma unroll
        for (int b = 0; b < NB2; b++) s += g_cnt2[b * NCLS + j];
        scount[j] = (float)s;
    }
    __syncthreads();

    // deterministic fixed-order reduction over second-level partials
    float sum = 0.0f;
#pragma unroll 8
    for (int b = 0; b < NB2; b++)
        sum += g_partials2[b * 1024 + j];

    const float mean = sum / scount[c];

    // per-class L2 norm: 256 threads/class = 8 warps/class
    float m2 = mean * mean;
#pragma unroll
    for (int o = 16; o > 0; o >>= 1)
        m2 += __shfl_down_sync(0xFFFFFFFFu, m2, o);
    if ((j & 31) == 0) wsum[j >> 5] = m2;
    __syncthreads();
    if (j < NCLS) {
        float t = 0.0f;
#pragma unroll
        for (int w = 0; w < 8; w++) t += wsum[j * 8 + w];
        float nrm = sqrtf(t);
        sinv[j] = 1.0f / fmaxf(nrm, 1e-12f);
    }
    __syncthreads();

    if (j < out_size) out[j] = mean * sinv[c];

    // target = arange(4), appended after the 1024 center floats if present
    int k = 1024 + j;
    if (j < NCLS && k < out_size) out[k] = (float)j;
}

extern "C" void kernel_launch(void* const* d_in, const int* in_sizes, int n_in,
                              void* d_out, int out_size)
{
    const ulonglong2* feat   = (const ulonglong2*)d_in[0];  // [N,256] f32
    const int*        labels = (const int*)d_in[1];         // [N] int32
    const int n = in_sizes[1];                              // rows

    seg_sum_kernel<<<NB, 256>>>(feat, labels, n);
    reduce_kernel<<<NB2, 1024>>>();
    finalize_kernel<<<1, 1024>>>((float*)d_out, out_size);
}

// round 16
// speedup vs baseline: 1.0756x; 1.0129x over previous
#include <cuda_runtime.h>
#include <cuda_bf16.h>
#include <cstdint>

// ---------------------------------------------------------------------------
// centercompute: per-class mean of [N, 256] f32 features (4 classes), then
// L2-normalize each class center. Output: fea_center [4,256] f32 (+ target
// arange(4) if out_size allows). Labels are int32 on device.
//
// Stage 1 (seg_sum, fused count): grid-stride over rows, 256 thr/block,
//   5 blocks/SM (grid 760 = 152*5, __launch_bounds__(256,5), regs<=51) for
//   occ 62% -> deeper HBM read queues. Thread t owns float4 column (t & 63);
//   its 4 unrolled rows are CONTIGUOUS so the 4 labels load as one aligned
//   int4. 64 thr/row -> warp-uniform label branch. Packed add.rn.f32x2
//   accumulate. col==0 threads count labels (integer). Block reduce ->
//   per-block partials (deterministic, no float atomics).
// Stage 2 (reduce): 40 blocks x 1024 thr each sum 19 stage-1 partial vectors
//   coalesced (760 = 40*19) -> 40 x 1024 floats; threads j<4 fold counts.
// Stage 3 (finalize): 1 block x 1024 thr sums 40 second-level partials +
//   40 counts in fixed order, normalizes, writes out.
// ---------------------------------------------------------------------------

#define NB   760        // stage-1 grid (152 SMs * 5)
#define NB2  40         // reduce grid; NB = NB2 * 19
#define REDW 19
#define NCLS 4

__device__ ulonglong2 g_partials [NB  * NCLS * 64]; // [block][class][64 x float4]
__device__ float      g_partials2[NB2 * 1024];      // [block2][class*256+col]
__device__ int        g_cnt [NB  * NCLS];
__device__ int        g_cnt2[NB2 * NCLS];

static __device__ __forceinline__ unsigned long long f32x2_add(
    unsigned long long a, unsigned long long b) {
    unsigned long long r;
    asm("add.rn.f32x2 %0, %1, %2;" : "=l"(r) : "l"(a), "l"(b));
    return r;
}

static __device__ __forceinline__ void vadd(ulonglong2& a, const ulonglong2& v) {
    a.x = f32x2_add(a.x, v.x);
    a.y = f32x2_add(a.y, v.y);
}

__global__ __launch_bounds__(256, 5) void seg_sum_kernel(
    const ulonglong2* __restrict__ feat,   // [N, 64] 16B packs (256 f32/row)
    const int*        __restrict__ labels, // [N] int32
    int n)
{
    const int tid  = threadIdx.x;
    const int col  = tid & 63;   // float4 column 0..63
    const int rsub = tid >> 6;   // row-quad slot 0..3 (rows rsub*4 .. rsub*4+3)

    ulonglong2 acc[NCLS];
#pragma unroll
    for (int c = 0; c < NCLS; c++) { acc[c].x = 0ull; acc[c].y = 0ull; }
    int cnt0 = 0, cnt1 = 0, cnt2 = 0, cnt3 = 0;   // used only when col==0

    const int stride = gridDim.x * 16;
    int base = blockIdx.x * 16;

    // ---- full-tile fast path: labels as one aligned int4 per thread ----
    for (; base + 16 <= n; base += stride) {
        const int r0 = base + rsub * 4;
        const int4 lab = *reinterpret_cast<const int4*>(labels + r0); // LDG.128, warp-bcast
        ulonglong2 v[4];
#pragma unroll
        for (int u = 0; u < 4; u++)                 // 4 independent LDG.128
            v[u] = feat[(size_t)(r0 + u) * 64 + col];

        int lv[4] = {lab.x, lab.y, lab.z, lab.w};
        // ---- warp-uniform class branch: adds for ONE class per row ----
#pragma unroll
        for (int u = 0; u < 4; u++) {
            int cl = lv[u];
            if      (cl == 0) vadd(acc[0], v[u]);
            else if (cl == 1) vadd(acc[1], v[u]);
            else if (cl == 2) vadd(acc[2], v[u]);
            else if (cl == 3) vadd(acc[3], v[u]);
        }
        if (col == 0) {
#pragma unroll
            for (int u = 0; u < 4; u++) {
                cnt0 += (lv[u] == 0); cnt1 += (lv[u] == 1);
                cnt2 += (lv[u] == 2); cnt3 += (lv[u] == 3);
            }
        }
    }

    // ---- tail: guarded scalar path ----
    if (base < n) {
        const int r0 = base + rsub * 4;
#pragma unroll
        for (int u = 0; u < 4; u++) {
            int r = r0 + u;
            if (r < n) {
                int cl = labels[r];
                ulonglong2 v = feat[(size_t)r * 64 + col];
                if      (cl == 0) vadd(acc[0], v);
                else if (cl == 1) vadd(acc[1], v);
                else if (cl == 2) vadd(acc[2], v);
                else if (cl == 3) vadd(acc[3], v);
                if (col == 0) {
                    cnt0 += (cl == 0); cnt1 += (cl == 1);
                    cnt2 += (cl == 2); cnt3 += (cl == 3);
                }
            }
        }
    }

    // ---- block reduction across the 4 row slots, write partials ----
    __shared__ ulonglong2 sh[256];
#pragma unroll
    for (int c = 0; c < NCLS; c++) {
        sh[tid] = acc[c];
        __syncthreads();
        if (tid < 64) {
            ulonglong2 s = sh[tid];
            vadd(s, sh[tid + 64]);
            vadd(s, sh[tid + 128]);
            vadd(s, sh[tid + 192]);
            g_partials[((size_t)blockIdx.x * NCLS + c) * 64 + tid] = s;
        }
        __syncthreads();
    }

    // ---- integer count reduction (4 contributing threads: tid 0,64,128,192)
    __shared__ int scnt[4 * NCLS];
    if (col == 0) {
        scnt[rsub * NCLS + 0] = cnt0;
        scnt[rsub * NCLS + 1] = cnt1;
        scnt[rsub * NCLS + 2] = cnt2;
        scnt[rsub * NCLS + 3] = cnt3;
    }
    __syncthreads();
    if (tid < NCLS)
        g_cnt[blockIdx.x * NCLS + tid] =
            scnt[tid] + scnt[NCLS + tid] + scnt[2 * NCLS + tid] + scnt[3 * NCLS + tid];
}

__global__ __launch_bounds__(1024) void reduce_kernel()
{
    const int j  = threadIdx.x;          // 0..1023 (class*256 + col)
    const int b0 = blockIdx.x * REDW;    // first stage-1 block of this slice
    const float* p = reinterpret_cast<const float*>(g_partials);

    float s = 0.0f;
#pragma unroll 4
    for (int k = 0; k < REDW; k++)       // coalesced: consecutive j -> consecutive floats
        s += p[(size_t)(b0 + k) * 1024 + j];
    g_partials2[blockIdx.x * 1024 + j] = s;

    // fold 19 count-vectors -> 1 (threads 0..3)
    if (j < NCLS) {
        int cs = 0;
#pragma unroll 4
        for (int k = 0; k < REDW; k++)
            cs += g_cnt[(b0 + k) * NCLS + j];
        g_cnt2[blockIdx.x * NCLS + j] = cs;
    }
}

__global__ __launch_bounds__(1024) void finalize_kernel(
    float* __restrict__ out, int out_size)
{
    __shared__ float scount[NCLS];
    __shared__ float wsum[32];
    __shared__ float sinv[NCLS];

    const int j = threadIdx.x;           // 0..1023
    const int c = j >> 8;                // class 0..3

    if (j < NCLS) {
        int s = 0;
#pragma unroll
        for (int b = 0; b < NB2; b++) s += g_cnt2[b * NCLS + j];
        scount[j] = (float)s;
    }
    __syncthreads();

    // deterministic fixed-order reduction over second-level partials
    float sum = 0.0f;
#pragma unroll 8
    for (int b = 0; b < NB2; b++)
        sum += g_partials2[b * 1024 + j];

    const float mean = sum / scount[c];

    // per-class L2 norm: 256 threads/class = 8 warps/class
    float m2 = mean * mean;
#pragma unroll
    for (int o = 16; o > 0; o >>= 1)
        m2 += __shfl_down_sync(0xFFFFFFFFu, m2, o);
    if ((j & 31) == 0) wsum[j >> 5] = m2;
    __syncthreads();
    if (j < NCLS) {
        float t = 0.0f;
#pragma unroll
        for (int w = 0; w < 8; w++) t += wsum[j * 8 + w];
        float nrm = sqrtf(t);
        sinv[j] = 1.0f / fmaxf(nrm, 1e-12f);
    }
    __syncthreads();

    if (j < out_size) out[j] = mean * sinv[c];

    // target = arange(4), appended after the 1024 center floats if present
    int k = 1024 + j;
    if (j < NCLS && k < out_size) out[k] = (float)j;
}

extern "C" void kernel_launch(void* const* d_in, const int* in_sizes, int n_in,
                              void* d_out, int out_size)
{
    const ulonglong2* feat   = (const ulonglong2*)d_in[0];  // [N,256] f32
    const int*        labels = (const int*)d_in[1];         // [N] int32
    const int n = in_sizes[1];                              // rows

    seg_sum_kernel<<<NB, 256>>>(feat, labels, n);
    reduce_kernel<<<NB2, 1024>>>();
    finalize_kernel<<<1, 1024>>>((float*)d_out, out_size);
}